// round 10
// baseline (speedup 1.0000x reference)
#include <cuda_runtime.h>

// Problem constants
#define BB 2
#define FF 512
#define HH 192
#define WW 192
#define TT 8
#define HW (HH * WW)

#define TILEX 32
#define TILEY 8
#define NZ 4
#define NTHREADS 1024
#define NWARPS 32
#define NPIX (TILEX * TILEY)   // 256 pixels/block, 4 threads each
#define MAXT 96                // texture staging capacity (typical survivors ~20)

__device__ __forceinline__ void cp_async16(void* dst_smem, const void* src_gmem) {
    unsigned saddr = (unsigned)__cvta_generic_to_shared(dst_smem);
    asm volatile("cp.async.cg.shared.global [%0], [%1], 16;\n"
                 :: "r"(saddr), "l"(src_gmem) : "memory");
}

__global__ __launch_bounds__(NTHREADS, 2)
void raster_kernel(const float* __restrict__ faces,
                   const float* __restrict__ textures,
                   float* __restrict__ out) {
    __shared__ float4 s_c0[FF];           // {A0,B0,C0,A1}   8 KB
    __shared__ float4 s_c1[FF];           // {B1,C1,iz0,iz1} 8 KB
    __shared__ float  s_iz2[FF];          // 2 KB
    __shared__ float4 s_tex[MAXT * 6];    // 9 KB
    __shared__ int    s_list[FF];         // 2 KB
    __shared__ int    s_cnt[NWARPS];
    __shared__ float  s_rinvd[NZ - 1][NPIX];   // 3 KB
    __shared__ int    s_ridx[NZ - 1][NPIX];    // 3 KB

    const int tid  = (threadIdx.z * TILEY + threadIdx.y) * TILEX + threadIdx.x;
    const int warp = tid >> 5;
    const int lane = tid & 31;
    const int b = blockIdx.z;

    // Tile bounds in NDC (pixel-center extremes)
    const int ix0 = blockIdx.x * TILEX;
    const int iy0 = blockIdx.y * TILEY;
    const float pxmin = (2.0f * (ix0 + 0.5f) - WW) / WW;
    const float pxmax = (2.0f * (ix0 + TILEX - 1 + 0.5f) - WW) / WW;
    const float pymin = (2.0f * (iy0 + 0.5f) - HH) / HH;
    const float pymax = (2.0f * (iy0 + TILEY - 1 + 0.5f) - HH) / HH;

    // --- Phase 0: threads 0..511 each test exactly ONE face.
    float x0, y0, z0, x1, y1, z1, x2, y2, z2, det;
    bool p = false;
    if (tid < FF) {
        const float* f = faces + ((size_t)b * FF + tid) * 9;
        x0 = f[0]; y0 = f[1]; z0 = f[2];
        x1 = f[3]; y1 = f[4]; z1 = f[5];
        x2 = f[6]; y2 = f[7]; z2 = f[8];
        det = (x1 - x0) * (y2 - y0) - (x2 - x0) * (y1 - y0);
        bool ok = fabsf(det) > 1e-8f;
        float xmin = fminf(x0, fminf(x1, x2)), xmax = fmaxf(x0, fmaxf(x1, x2));
        float ymin = fminf(y0, fminf(y1, y2)), ymax = fmaxf(y0, fmaxf(y1, y2));
        p = ok && (xmin <= pxmax) && (xmax >= pxmin) && (ymin <= pymax) && (ymax >= pymin);
    }

    // --- Phase 1: order-preserving warp compaction; survivors compute coefs.
    unsigned ball = __ballot_sync(0xffffffffu, p);
    if (lane == 0) s_cnt[warp] = __popc(ball);
    __syncthreads();

    int offset = 0, total = 0;
    #pragma unroll
    for (int w = 0; w < NWARPS; w++) {
        int c = s_cnt[w];
        if (w < warp) offset += c;
        total += c;
    }

    if (p) {
        int s = offset + __popc(ball & ((1u << lane) - 1u));
        float inv_det = 1.0f / det;
        s_list[s] = tid;
        s_c0[s] = make_float4((x1 * y2 - x2 * y1) * inv_det,
                              (y1 - y2) * inv_det,
                              (x2 - x1) * inv_det,
                              (x2 * y0 - x0 * y2) * inv_det);
        s_c1[s] = make_float4((y2 - y0) * inv_det,
                              (x0 - x2) * inv_det,
                              1.0f / z0, 1.0f / z1);
        s_iz2[s] = 1.0f / z2;
    }
    __syncthreads();

    // --- Phase 2: async texture staging for survivors (awaited before epilogue).
    {
        int ntex = (total < MAXT ? total : MAXT) * 6;
        const float4* txg = (const float4*)(textures + (size_t)b * FF * 3 * TT);
        for (int i = tid; i < ntex; i += NTHREADS) {
            int s = i / 6, part = i - s * 6;
            cp_async16(&s_tex[i], &txg[s_list[s] * 6 + part]);
        }
        asm volatile("cp.async.commit_group;\n" ::: "memory");
    }

    // --- Phase 3: z-test. Each thread: 1 pixel, quarter of the list.
    const int ix = ix0 + threadIdx.x;
    const int iy = iy0 + threadIdx.y;
    const float px = (2.0f * (ix + 0.5f) - WW) / WW;
    const float py = (2.0f * (iy + 0.5f) - HH) / HH;

    const int iBeg = (threadIdx.z * total) >> 2;
    const int iEnd = ((threadIdx.z + 1) * total) >> 2;

    float best_invd = 0.01f;   // 1/FAR sentinel (must strictly beat => depth < FAR)
    int best = -1;
    for (int i = iBeg; i < iEnd; i++) {
        float4 c0 = s_c0[i];
        float4 c1 = s_c1[i];
        float iz2 = s_iz2[i];
        float w0 = fmaf(c0.z, py, fmaf(c0.y, px, c0.x));
        float w1 = fmaf(c1.y, py, fmaf(c1.x, px, c0.w));
        float w2 = 1.0f - w0 - w1;
        float invd = fmaf(w2, iz2, fmaf(w1, c1.w, w0 * c1.z));
        float wmin = fminf(w0, fminf(w1, w2));
        if (wmin >= 0.0f && invd > best_invd) { best_invd = invd; best = i; }
    }

    // --- Reduce the 4 z-slices; await texture staging.
    asm volatile("cp.async.wait_group 0;\n" ::: "memory");
    const int pidx = threadIdx.y * TILEX + threadIdx.x;
    if (threadIdx.z) {
        s_rinvd[threadIdx.z - 1][pidx] = best_invd;
        s_ridx[threadIdx.z - 1][pidx]  = best;
    }
    __syncthreads();
    if (threadIdx.z) return;

    #pragma unroll
    for (int zz = 0; zz < NZ - 1; zz++) {
        float oi = s_rinvd[zz][pidx];
        // strict >: lower z-slice (earlier list indices) wins ties -> argmin-first
        if (oi > best_invd) { best_invd = oi; best = s_ridx[zz][pidx]; }
    }

    // --- Epilogue: interpolate + coalesced writes (32-wide rows; warps 0-7).
    const int pix = iy * WW + ix;
    float* feature = out;                      // (B, 9, H, W)
    float* fim  = out + (size_t)BB * 9 * HW;   // (B, H, W) as float
    float* dmap = fim + (size_t)BB * HW;       // (B, H, W)
    float* fptr = feature + (size_t)b * 9 * HW + pix;

    if (best >= 0) {
        float4 c0 = s_c0[best];
        float4 c1 = s_c1[best];
        float w0 = fmaf(c0.z, py, fmaf(c0.y, px, c0.x));
        float w1 = fmaf(c1.y, py, fmaf(c1.x, px, c0.w));
        float w2 = 1.0f - w0 - w1;
        int f = s_list[best];
        float4 t0a, t0b, t1a, t1b, t2a, t2b;
        if (best < MAXT) {
            t0a = s_tex[best * 6 + 0]; t0b = s_tex[best * 6 + 1];
            t1a = s_tex[best * 6 + 2]; t1b = s_tex[best * 6 + 3];
            t2a = s_tex[best * 6 + 4]; t2b = s_tex[best * 6 + 5];
        } else {
            const float4* tx = (const float4*)(textures + ((size_t)(b * FF + f) * 3) * TT);
            t0a = tx[0]; t0b = tx[1]; t1a = tx[2]; t1b = tx[3]; t2a = tx[4]; t2b = tx[5];
        }
        float r[8];
        r[0] = w0 * t0a.x + w1 * t1a.x + w2 * t2a.x;
        r[1] = w0 * t0a.y + w1 * t1a.y + w2 * t2a.y;
        r[2] = w0 * t0a.z + w1 * t1a.z + w2 * t2a.z;
        r[3] = w0 * t0a.w + w1 * t1a.w + w2 * t2a.w;
        r[4] = w0 * t0b.x + w1 * t1b.x + w2 * t2b.x;
        r[5] = w0 * t0b.y + w1 * t1b.y + w2 * t2b.y;
        r[6] = w0 * t0b.z + w1 * t1b.z + w2 * t2b.z;
        r[7] = w0 * t0b.w + w1 * t1b.w + w2 * t2b.w;
        #pragma unroll
        for (int t = 0; t < 8; t++) fptr[(size_t)t * HW] = r[t];
        fptr[(size_t)8 * HW] = 1.0f;
        fim[(size_t)b * HW + pix]  = (float)f;
        dmap[(size_t)b * HW + pix] = 1.0f / best_invd;
    } else {
        #pragma unroll
        for (int t = 0; t < 8; t++) fptr[(size_t)t * HW] = 0.0f;
        fptr[(size_t)8 * HW] = 0.0f;
        fim[(size_t)b * HW + pix]  = -1.0f;
        dmap[(size_t)b * HW + pix] = 100.0f;  // FAR
    }
}

extern "C" void kernel_launch(void* const* d_in, const int* in_sizes, int n_in,
                              void* d_out, int out_size) {
    const float* faces    = (const float*)d_in[0];    // (B, F, 3, 3)
    const float* textures = (const float*)d_in[1];    // (B, F, 3, T)
    float* out = (float*)d_out;

    dim3 blk(TILEX, TILEY, NZ);
    dim3 grd(WW / TILEX, HH / TILEY, BB);
    raster_kernel<<<grd, blk>>>(faces, textures, out);
}

// round 12
// speedup vs baseline: 1.2294x; 1.2294x over previous
#include <cuda_runtime.h>

// Problem constants
#define BB 2
#define FF 512
#define HH 192
#define WW 192
#define TT 8
#define HW (HH * WW)

#define TILEX 32
#define TILEY 8
#define NZ 2
#define NTHREADS 512
#define NWARPS 16
#define NPIX (TILEX * TILEY)   // 256 pixels/block, 2 threads each
#define MAXT 96                // texture staging capacity (typical survivors ~20)

__device__ __forceinline__ void cp_async16(void* dst_smem, const void* src_gmem) {
    unsigned saddr = (unsigned)__cvta_generic_to_shared(dst_smem);
    asm volatile("cp.async.cg.shared.global [%0], [%1], 16;\n"
                 :: "r"(saddr), "l"(src_gmem) : "memory");
}

__global__ __launch_bounds__(NTHREADS, 2)
void raster_kernel(const float* __restrict__ faces,
                   const float* __restrict__ textures,
                   float* __restrict__ out) {
    __shared__ float4 s_c0[FF];           // {A0,B0,C0,A1}   8 KB
    __shared__ float4 s_c1[FF];           // {B1,C1,iz0,iz1} 8 KB
    __shared__ float  s_iz2[FF];          // 2 KB
    __shared__ float4 s_tex[MAXT * 6];    // 9 KB
    __shared__ int    s_list[FF];         // 2 KB
    __shared__ int    s_cnt[NWARPS];
    __shared__ float  s_rinvd[NPIX];      // 1 KB
    __shared__ int    s_ridx[NPIX];       // 1 KB

    const int tid  = (threadIdx.z * TILEY + threadIdx.y) * TILEX + threadIdx.x;
    const int warp = tid >> 5;
    const int lane = tid & 31;
    const int b = blockIdx.z;

    // Tile bounds in NDC (pixel-center extremes)
    const int ix0 = blockIdx.x * TILEX;
    const int iy0 = blockIdx.y * TILEY;
    const float pxmin = (2.0f * (ix0 + 0.5f) - WW) / WW;
    const float pxmax = (2.0f * (ix0 + TILEX - 1 + 0.5f) - WW) / WW;
    const float pymin = (2.0f * (iy0 + 0.5f) - HH) / HH;
    const float pymax = (2.0f * (iy0 + TILEY - 1 + 0.5f) - HH) / HH;

    // --- Phase 0: every thread tests exactly ONE face (512 threads, 512 faces).
    float x0, y0, z0, x1, y1, z1, x2, y2, z2, det;
    bool p;
    {
        const float* f = faces + ((size_t)b * FF + tid) * 9;
        x0 = f[0]; y0 = f[1]; z0 = f[2];
        x1 = f[3]; y1 = f[4]; z1 = f[5];
        x2 = f[6]; y2 = f[7]; z2 = f[8];
        det = (x1 - x0) * (y2 - y0) - (x2 - x0) * (y1 - y0);
        bool ok = fabsf(det) > 1e-8f;
        float xmin = fminf(x0, fminf(x1, x2)), xmax = fmaxf(x0, fmaxf(x1, x2));
        float ymin = fminf(y0, fminf(y1, y2)), ymax = fmaxf(y0, fmaxf(y1, y2));
        p = ok && (xmin <= pxmax) && (xmax >= pxmin) && (ymin <= pymax) && (ymax >= pymin);
    }

    // --- Phase 1: order-preserving compaction (shfl-scan of warp counts).
    unsigned ball = __ballot_sync(0xffffffffu, p);
    if (lane == 0) s_cnt[warp] = __popc(ball);
    __syncthreads();

    int offset, total;
    {
        int c = s_cnt[lane & (NWARPS - 1)];
        #pragma unroll
        for (int d = 1; d < NWARPS; d <<= 1) {
            int n = __shfl_up_sync(0xffffffffu, c, d);
            if ((lane & (NWARPS - 1)) >= d) c += n;
        }
        total  = __shfl_sync(0xffffffffu, c, NWARPS - 1);
        offset = (warp == 0) ? 0 : __shfl_sync(0xffffffffu, c, warp - 1);
    }

    if (p) {
        int s = offset + __popc(ball & ((1u << lane) - 1u));
        float inv_det = 1.0f / det;
        s_list[s] = tid;
        s_c0[s] = make_float4((x1 * y2 - x2 * y1) * inv_det,
                              (y1 - y2) * inv_det,
                              (x2 - x1) * inv_det,
                              (x2 * y0 - x0 * y2) * inv_det);
        s_c1[s] = make_float4((y2 - y0) * inv_det,
                              (x0 - x2) * inv_det,
                              1.0f / z0, 1.0f / z1);
        s_iz2[s] = 1.0f / z2;
    }
    __syncthreads();

    // --- Phase 2: async texture staging for survivors (awaited before epilogue).
    {
        int ntex = (total < MAXT ? total : MAXT) * 6;
        const float4* txg = (const float4*)(textures + (size_t)b * FF * 3 * TT);
        for (int i = tid; i < ntex; i += NTHREADS) {
            int s = i / 6, part = i - s * 6;
            cp_async16(&s_tex[i], &txg[s_list[s] * 6 + part]);
        }
        asm volatile("cp.async.commit_group;\n" ::: "memory");
    }

    // --- Phase 3: z-test. Each thread: 1 pixel, half of the list.
    const int ix = ix0 + threadIdx.x;
    const int iy = iy0 + threadIdx.y;
    const float px = (2.0f * (ix + 0.5f) - WW) / WW;
    const float py = (2.0f * (iy + 0.5f) - HH) / HH;

    const int half = (total + 1) >> 1;
    const int iBeg = threadIdx.z ? half : 0;
    const int iEnd = threadIdx.z ? total : half;

    float best_invd = 0.01f;   // 1/FAR sentinel (strictly beat => depth < FAR)
    int best = -1;
    for (int i = iBeg; i < iEnd; i++) {
        float4 c0 = s_c0[i];
        float4 c1 = s_c1[i];
        float iz2 = s_iz2[i];
        float w0 = fmaf(c0.z, py, fmaf(c0.y, px, c0.x));
        float w1 = fmaf(c1.y, py, fmaf(c1.x, px, c0.w));
        float w2 = 1.0f - w0 - w1;
        float invd = fmaf(w2, iz2, fmaf(w1, c1.w, w0 * c1.z));
        float wmin = fminf(w0, fminf(w1, w2));
        if (wmin >= 0.0f && invd > best_invd) { best_invd = invd; best = i; }
    }

    // --- Reduce the 2 z-slices; await texture staging.
    asm volatile("cp.async.wait_group 0;\n" ::: "memory");
    const int pidx = threadIdx.y * TILEX + threadIdx.x;
    if (threadIdx.z) {
        s_rinvd[pidx] = best_invd;
        s_ridx[pidx]  = best;
    }
    __syncthreads();
    if (threadIdx.z) return;

    {
        float oi = s_rinvd[pidx];
        // strict >: low half (earlier list indices) wins ties -> argmin-first
        if (oi > best_invd) { best_invd = oi; best = s_ridx[pidx]; }
    }

    // --- Epilogue: interpolate + coalesced writes (32-wide rows).
    const int pix = iy * WW + ix;
    float* feature = out;                      // (B, 9, H, W)
    float* fim  = out + (size_t)BB * 9 * HW;   // (B, H, W) as float
    float* dmap = fim + (size_t)BB * HW;       // (B, H, W)
    float* fptr = feature + (size_t)b * 9 * HW + pix;

    if (best >= 0) {
        float4 c0 = s_c0[best];
        float4 c1 = s_c1[best];
        float w0 = fmaf(c0.z, py, fmaf(c0.y, px, c0.x));
        float w1 = fmaf(c1.y, py, fmaf(c1.x, px, c0.w));
        float w2 = 1.0f - w0 - w1;
        int f = s_list[best];
        float4 t0a, t0b, t1a, t1b, t2a, t2b;
        if (best < MAXT) {
            t0a = s_tex[best * 6 + 0]; t0b = s_tex[best * 6 + 1];
            t1a = s_tex[best * 6 + 2]; t1b = s_tex[best * 6 + 3];
            t2a = s_tex[best * 6 + 4]; t2b = s_tex[best * 6 + 5];
        } else {
            const float4* tx = (const float4*)(textures + ((size_t)(b * FF + f) * 3) * TT);
            t0a = tx[0]; t0b = tx[1]; t1a = tx[2]; t1b = tx[3]; t2a = tx[4]; t2b = tx[5];
        }
        float r[8];
        r[0] = w0 * t0a.x + w1 * t1a.x + w2 * t2a.x;
        r[1] = w0 * t0a.y + w1 * t1a.y + w2 * t2a.y;
        r[2] = w0 * t0a.z + w1 * t1a.z + w2 * t2a.z;
        r[3] = w0 * t0a.w + w1 * t1a.w + w2 * t2a.w;
        r[4] = w0 * t0b.x + w1 * t1b.x + w2 * t2b.x;
        r[5] = w0 * t0b.y + w1 * t1b.y + w2 * t2b.y;
        r[6] = w0 * t0b.z + w1 * t1b.z + w2 * t2b.z;
        r[7] = w0 * t0b.w + w1 * t1b.w + w2 * t2b.w;
        #pragma unroll
        for (int t = 0; t < 8; t++) fptr[(size_t)t * HW] = r[t];
        fptr[(size_t)8 * HW] = 1.0f;
        fim[(size_t)b * HW + pix]  = (float)f;
        dmap[(size_t)b * HW + pix] = 1.0f / best_invd;
    } else {
        #pragma unroll
        for (int t = 0; t < 8; t++) fptr[(size_t)t * HW] = 0.0f;
        fptr[(size_t)8 * HW] = 0.0f;
        fim[(size_t)b * HW + pix]  = -1.0f;
        dmap[(size_t)b * HW + pix] = 100.0f;  // FAR
    }
}

extern "C" void kernel_launch(void* const* d_in, const int* in_sizes, int n_in,
                              void* d_out, int out_size) {
    const float* faces    = (const float*)d_in[0];    // (B, F, 3, 3)
    const float* textures = (const float*)d_in[1];    // (B, F, 3, T)
    float* out = (float*)d_out;

    dim3 blk(TILEX, TILEY, NZ);
    dim3 grd(WW / TILEX, HH / TILEY, BB);
    raster_kernel<<<grd, blk>>>(faces, textures, out);
}